// round 15
// baseline (speedup 1.0000x reference)
#include <cuda_runtime.h>
#include <cuda_bf16.h>
#include <cuda_fp16.h>
#include <cstdint>

#define N_SAMP   262144
#define ZD       2
#define CTX      128
#define HID      128
#define TEMB     32
#define NSTEPS   50
#define SPB      128     // samples per block
#define NTHREADS 256     // 8 warps: 4 diffusion + 4 cnf, 32 samples each

// output layout: traj [51,N,2] | us [50,N,2] | times [51]
#define US_OFF    ((long long)(NSTEPS+1) * N_SAMP * ZD)
#define TAIL_OFF  (US_OFF + (long long)NSTEPS * N_SAMP * ZD)

// per-step tw constants (PRE-HALVED fp32), permuted into per-lane fragment order:
// idx = i*128 + kt*16 + t*4 + comp,  comp = reg*2 + half  (k = kt*16 + 2t + reg*8 + half)
__device__ float g_twd[NSTEPS * HID];
__device__ float g_twc[NSTEPS * HID];
__device__ float g_dts[NSTEPS];
__device__ float g_coef[NSTEPS];

__device__ __forceinline__ __half2 u2h2(uint32_t u) { return *reinterpret_cast<__half2*>(&u); }

// pack two fp32 -> fp16x2: lower half = 'even', upper = 'odd'
__device__ __forceinline__ uint32_t cvt2h(float odd_k, float even_k) {
    uint32_t r; asm("cvt.rn.f16x2.f32 %0, %1, %2;" : "=r"(r) : "f"(odd_k), "f"(even_k)); return r;
}
__device__ __forceinline__ uint32_t tanh2u(uint32_t x) {
    uint32_t r; asm("tanh.approx.f16x2 %0, %1;" : "=r"(r) : "r"(x)); return r;
}
__device__ __forceinline__ void mma16816h(float* d, uint32_t a0, uint32_t a1,
                                          uint32_t a2, uint32_t a3,
                                          uint32_t b0, uint32_t b1) {
    asm volatile("mma.sync.aligned.m16n8k16.row.col.f32.f16.f16.f32 "
                 "{%0,%1,%2,%3}, {%4,%5,%6,%7}, {%8,%9}, {%0,%1,%2,%3};"
                 : "+f"(d[0]), "+f"(d[1]), "+f"(d[2]), "+f"(d[3])
                 : "r"(a0), "r"(a1), "r"(a2), "r"(a3), "r"(b0), "r"(b1));
}
__device__ __forceinline__ void mbar_init(uint32_t addr, uint32_t cnt) {
    asm volatile("mbarrier.init.shared.b64 [%0], %1;" :: "r"(addr), "r"(cnt) : "memory");
}
__device__ __forceinline__ void mbar_arrive(uint32_t addr) {
    asm volatile("mbarrier.arrive.release.cta.shared::cta.b64 _, [%0];" :: "r"(addr) : "memory");
}
__device__ __forceinline__ void mbar_wait(uint32_t addr, uint32_t parity) {
    asm volatile("{\n\t"
                 ".reg .pred P1;\n\t"
                 "WAIT_%=:\n\t"
                 "mbarrier.try_wait.parity.acquire.cta.shared::cta.b64 P1, [%0], %1, 0x989680;\n\t"
                 "@P1 bra.uni DONE_%=;\n\t"
                 "bra.uni WAIT_%=;\n\t"
                 "DONE_%=:\n\t"
                 "}"
                 :: "r"(addr), "r"(parity) : "memory");
}

// fragment position helpers (k within 128): kt = k>>4, kr = k&15
// t = (kr&7)>>1, reg = (kr>>3)&1, half = kr&1, comp = reg*2 + half
__host__ __device__ __forceinline__ int frag_comp(int kr) { return (((kr >> 3) & 1) << 1) | (kr & 1); }

// ---------------------------------------------------------------------------
// Kernel A: per-step constants (PRE-HALVED tw, permuted) + times tail
// ---------------------------------------------------------------------------
__global__ void prep_kernel(const float* __restrict__ times,
                            const float* __restrict__ freqs,
                            const float* __restrict__ dW1, const float* __restrict__ db1,
                            const float* __restrict__ cW1, const float* __restrict__ cb1,
                            const float* __restrict__ log_diff,
                            float* __restrict__ out)
{
    __shared__ float temb[TEMB];
    int tid = threadIdx.x;  // 128 threads, tid = k
    if (tid < NSTEPS + 1) out[TAIL_OFF + tid] = times[tid];
    int kt = tid >> 4, kr = tid & 15;
    int pidx = kt * 16 + ((kr & 7) >> 1) * 4 + frag_comp(kr);  // permuted position
    float gb = log1pf(__expf(log_diff[0]));  // softplus
    for (int i = 0; i < NSTEPS; i++) {
        float t = times[i];
        __syncthreads();
        if (tid < TEMB / 2) {
            float a = 6.2831853071795864f * t * freqs[tid];
            temb[tid]            = sinf(a);
            temb[tid + TEMB / 2] = cosf(a);
        }
        __syncthreads();
        float ad = db1[tid], ac = cb1[tid];
#pragma unroll 8
        for (int mm = 0; mm < TEMB; mm++) {
            float tv = temb[mm];
            ad += tv * dW1[(ZD + CTX + mm) * HID + tid];
            ac += tv * cW1[(ZD + CTX + mm) * HID + tid];
        }
        g_twd[i * HID + pidx] = 0.5f * ad;   // pre-halved (fp32, exact rescale)
        g_twc[i * HID + pidx] = 0.5f * ac;
        if (tid == 0) {
            float dt = times[i + 1] - t;
            g_dts[i]  = dt;
            g_coef[i] = gb * (1.0f - t) * sqrtf(fmaxf(dt, 1e-12f));
        }
    }
}

// ---------------------------------------------------------------------------
// base = ctx @ W1[2:130] for one group of 8 samples, ctx read from GMEM (fp32)
// ---------------------------------------------------------------------------
__device__ __forceinline__ void compute_base(float* __restrict__ dst,
                                             const float* __restrict__ ctxg,
                                             const float* __restrict__ W1,
                                             int grp, int l)
{
    float acc[8][4];
#pragma unroll
    for (int s8 = 0; s8 < 8; s8++)
#pragma unroll
        for (int c = 0; c < 4; c++) acc[s8][c] = 0.f;
#pragma unroll 2
    for (int r = 0; r < CTX; r++) {
        float w1v[4];
#pragma unroll
        for (int c = 0; c < 4; c++) w1v[c] = W1[(ZD + r) * HID + l + 32 * c];
#pragma unroll
        for (int s8 = 0; s8 < 8; s8++) {
            float a = __ldg(&ctxg[(long long)(grp * 8 + s8) * HID + r]);
#pragma unroll
            for (int c = 0; c < 4; c++) acc[s8][c] += a * w1v[c];
        }
    }
#pragma unroll
    for (int s8 = 0; s8 < 8; s8++)
#pragma unroll
        for (int c = 0; c < 4; c++)
            dst[(grp * 8 + s8) * HID + l + 32 * c] = acc[s8][c];
}

// ---------------------------------------------------------------------------
// Kernel B: persistent 50-step SDE, fp16 tensor-core layer-2, SPB=128.
// 256 threads, 8 warps: m = w&1 (MLP), wg = w>>1 (0..3). Each warp carries
// 32 REAL samples (4 sub-blocks of 8: rows g, g+8, g+16, g+24) as TWO
// m16n8k16 row-blocks sharing every B-fragment load -> per-sample B traffic
// halves vs R14. 255-reg budget enables Af[2][8][4] + d[2][8][4].
// Layer-1/epilogue: fp32 arithmetic, tanh via f16x2 (R14 numerics unchanged).
// Step sync: pairwise mbarrier handshake, no CTA barrier in the loop.
// SMEM: BfD(32K) BfC(32K) baseRD(64K) baseRC(64K) + tables + psum ~ 201KB.
// ---------------------------------------------------------------------------
__global__ void __launch_bounds__(NTHREADS, 1)
sde_kernel(const float* __restrict__ z0,
           const float* __restrict__ pctx, const float* __restrict__ cctx,
           const float* __restrict__ noise,
           const float* __restrict__ dW1, const float* __restrict__ dW2,
           const float* __restrict__ db2, const float* __restrict__ dW3,
           const float* __restrict__ db3,
           const float* __restrict__ cW1, const float* __restrict__ cW2,
           const float* __restrict__ cb2, const float* __restrict__ cW3,
           const float* __restrict__ cb3,
           float* __restrict__ out)
{
    extern __shared__ float sm[];
    uint4* BfD    = (uint4*)sm;              // 8kt*8ntp*32lane uint4 = 32KB
    uint4* BfC    = BfD + 2048;              // 32KB
    float* baseRD = (float*)(BfC + 2048);    // 4 swg * 8 kt * 4 sub * 32 lane * 4 = 64KB
    float* baseRC = baseRD + 16384;          // 64KB
    float* wzRs   = baseRC + 16384;          // [mlp][row][kt][t] float4 = 512 f (pre-halved)
    float* b2Rs   = wzRs + 512;              // [mlp][ntg][t] float2 = 256 f (pre-halved)
    float* W3Rs   = b2Rs + 256;              // [mlp][ntg][t] float4 = 512 f
    float2* psum2 = (float2*)(W3Rs + 512);   // [2 buf][2 mlp][128] float2 = 4KB
    // mbarriers: [2 mlp][4 wg][2 buf] u64 = 128B
    unsigned long long* mbars = (unsigned long long*)(psum2 + 512);

    int tid = threadIdx.x;
    int w = tid >> 5, l = tid & 31;
    int m  = w & 1;        // 0 = diffusion (u), 1 = cnf (f)  [SMSP-aware map]
    int wg = w >> 1;       // sample group of 32 (0..3)
    int t3 = l & 3;        // quad thread
    int g  = l >> 2;       // row 0-7; samples = wg*32 + g + sub*8, sub=0..3
    int blockBase = blockIdx.x * SPB;
    int s0 = wg * 32 + g;  // sub 0 sample (within CTA)

    // ================= phase 1 =================
    // 1) base in [s][k] layout, ctx read directly from gmem (4 groups per warp)
    {
        const float* ctxg = (m ? cctx : pctx) + (long long)blockBase * HID;
        const float* W1g  = m ? cW1 : dW1;
        float* dst = m ? baseRC : baseRD;
        compute_base(dst, ctxg, W1g, wg * 4 + 0, l);
        compute_base(dst, ctxg, W1g, wg * 4 + 1, l);
        compute_base(dst, ctxg, W1g, wg * 4 + 2, l);
        compute_base(dst, ctxg, W1g, wg * 4 + 3, l);
    }
    __syncthreads();
    // 2) in-place permute base -> fragment order, PRE-HALVED (fp32):
    //    ni = (((swg*8 + kt)*4 + sub)*32 + lane)*4 + comp
    {
        float tmpv[64];
#pragma unroll
        for (int a = 0; a < 2; a++) {
            float* arr = a ? baseRC : baseRD;
#pragma unroll
            for (int q = 0; q < 64; q++) tmpv[q] = arr[tid * 64 + q];
            __syncthreads();
#pragma unroll
            for (int q = 0; q < 64; q++) {
                int idx = tid * 64 + q;
                int s = idx >> 7, k = idx & 127;
                int swg = s >> 5, srow = s & 31;
                int sub = srow >> 3, gg = srow & 7;
                int kt = k >> 4, kr = k & 15;
                int lane = gg * 4 + ((kr & 7) >> 1);
                int ni = (((swg * 8 + kt) * 4 + sub) * 32 + lane) * 4 + frag_comp(kr);
                arr[ni] = 0.5f * tmpv[q];
            }
            __syncthreads();
        }
    }
    // 3) W2 -> SINGLE fp16 in B-fragment layout (two ntg per uint4); tables; mbars
    {
        unsigned short* bD16 = (unsigned short*)BfD;
        unsigned short* bC16 = (unsigned short*)BfC;
        for (int e = tid; e < HID * HID; e += NTHREADS) {
            int k = e >> 7, j = e & 127;
            int kt = k >> 4, kr = k & 15;
            int reg = (kr >> 3) & 1, half = kr & 1;
            int lane = (j & 7) * 4 + ((kr & 7) >> 1);
            int ntg = j >> 3;
            int ntp = ntg >> 1, sub = ntg & 1;
            int slot = ((kt * 8 + ntp) * 32 + lane) * 4 + sub * 2 + reg;
            bD16[slot * 2 + half] = __half_as_ushort(__float2half_rn(dW2[e]));
            bC16[slot * 2 + half] = __half_as_ushort(__float2half_rn(cW2[e]));
        }
        // wzR (PRE-HALVED): [mlp][row][kt][t][comp]
        for (int idx = tid; idx < 2 * 2 * HID; idx += NTHREADS) {
            int mlp = idx >> 8, row = (idx >> 7) & 1, k = idx & 127;
            int kt = k >> 4, kr = k & 15;
            float v = 0.5f * (mlp ? cW1 : dW1)[row * HID + k];
            wzRs[((mlp * 2 + row) * 8 + kt) * 16 + ((kr & 7) >> 1) * 4 + frag_comp(kr)] = v;
        }
        // b2R (PRE-HALVED): [mlp][ntg][t][half]   (j = ntg*8 + 2t + half)
        for (int idx = tid; idx < 2 * HID; idx += NTHREADS) {
            int mlp = idx >> 7, j = idx & 127;
            float v = 0.5f * (mlp ? cb2 : db2)[j];
            b2Rs[(mlp * 16 + (j >> 3)) * 8 + ((j & 7) >> 1) * 2 + (j & 1)] = v;
        }
        // W3R: [mlp][ntg][t][(j&1)*2 + d]
        for (int idx = tid; idx < 2 * HID * ZD; idx += NTHREADS) {
            int mlp = idx >> 8, j = (idx >> 1) & 127, d = idx & 1;
            float v = (mlp ? cW3 : dW3)[j * ZD + d];
            W3Rs[(mlp * 16 + (j >> 3)) * 16 + ((j & 7) >> 1) * 4 + (j & 1) * 2 + d] = v;
        }
        // 16 mbarriers, arrive count = 8 (the t3==0 lanes of one warp)
        if (tid < 16)
            mbar_init((uint32_t)__cvta_generic_to_shared(&mbars[tid]), 8);
    }
    __syncthreads();

    // ================= per-warp constant pointers / regs =================
    const uint4*  Bf    = m ? BfC : BfD;
    const float4* bR4   = (const float4*)(m ? baseRC : baseRD);
    const float4* twR4  = (const float4*)(m ? g_twc : g_twd);
    const float4* wz04  = (const float4*)wzRs + (m * 2 + 0) * 32;
    const float4* wz14  = (const float4*)wzRs + (m * 2 + 1) * 32;
    const float2* b2R2  = (const float2*)b2Rs + m * 64;
    const float4* W3R4  = (const float4*)W3Rs + m * 64;
    const float2* noise2 = (const float2*)noise;
    float2* outTraj = (float2*)out;
    float2* outUS   = (float2*)(out + US_OFF);

    uint32_t myBar0   = (uint32_t)__cvta_generic_to_shared(&mbars[(m * 4 + wg) * 2 + 0]);
    uint32_t myBar1   = (uint32_t)__cvta_generic_to_shared(&mbars[(m * 4 + wg) * 2 + 1]);
    uint32_t peerBar0 = (uint32_t)__cvta_generic_to_shared(&mbars[((1 - m) * 4 + wg) * 2 + 0]);
    uint32_t peerBar1 = (uint32_t)__cvta_generic_to_shared(&mbars[((1 - m) * 4 + wg) * 2 + 1]);

    float b3_0, b3_1;
    { const float* b3 = m ? cb3 : db3; b3_0 = b3[0]; b3_1 = b3[1]; }

    // init z for 4 sub-blocks (all 4 lanes of quad hold each sample's z)
    float zS0[4], zS1[4];
#pragma unroll
    for (int sub = 0; sub < 4; sub++) {
        int gs = blockBase + s0 + sub * 8;
        float2 zi = __ldg(&((const float2*)z0)[gs]);
        zS0[sub] = zi.x; zS1[sub] = zi.y;
        if (m == 1 && t3 == 0) outTraj[gs] = zi;  // traj[0]
    }

    // ================= 50-step loop (no CTA barrier inside) =================
    for (int i = 0; i < NSTEPS; i++) {
        float dt = g_dts[i], cf = g_coef[i];
        long long io = (long long)i * N_SAMP;
        float2 xi[4];
#pragma unroll
        for (int sub = 0; sub < 4; sub++)
            xi[sub] = __ldg(&noise2[io + blockBase + s0 + sub * 8]);

        // ---- layer 1 (fp32 h2 = x/2; tanh via f16x2) -> A frags for 2 blocks ----
        uint32_t Af0[8][4], Af1[8][4];
#pragma unroll
        for (int kt = 0; kt < 8; kt++) {
            float4 tw = __ldg(&twR4[i * 32 + kt * 4 + t3]);   // pre-halved
            float4 w0 = wz04[kt * 4 + t3];                    // pre-halved
            float4 w1 = wz14[kt * 4 + t3];
            uint32_t pk[4][2];
#pragma unroll
            for (int sub = 0; sub < 4; sub++) {
                float4 bs = bR4[(((wg * 8 + kt) * 4 + sub) * 32) + l];  // pre-halved
                float zx = zS0[sub], zy = zS1[sub];
                float h0 = bs.x + tw.x + zx * w0.x + zy * w1.x;  // = x/2
                float h1 = bs.y + tw.y + zx * w0.y + zy * w1.y;
                float h2 = bs.z + tw.z + zx * w0.z + zy * w1.z;
                float h3 = bs.w + tw.w + zx * w0.w + zy * w1.w;
                uint32_t t01 = tanh2u(cvt2h(h1, h0));
                uint32_t t23 = tanh2u(cvt2h(h3, h2));
                float2 f01 = __half22float2(u2h2(t01));
                float2 f23 = __half22float2(u2h2(t23));
                float x0 = fmaf(h0, f01.x, h0);
                float x1 = fmaf(h1, f01.y, h1);
                float x2 = fmaf(h2, f23.x, h2);
                float x3 = fmaf(h3, f23.y, h3);
                pk[sub][0] = cvt2h(x1, x0);
                pk[sub][1] = cvt2h(x3, x2);
            }
            Af0[kt][0] = pk[0][0]; Af0[kt][1] = pk[1][0]; Af0[kt][2] = pk[0][1]; Af0[kt][3] = pk[1][1];
            Af1[kt][0] = pk[2][0]; Af1[kt][1] = pk[3][0]; Af1[kt][2] = pk[2][1]; Af1[kt][3] = pk[3][1];
        }

        // ---- layer 2 + epilogue in two N passes; B loads shared by both blocks ----
        float acc0[4], acc1[4];
#pragma unroll
        for (int sub = 0; sub < 4; sub++) { acc0[sub] = 0.f; acc1[sub] = 0.f; }
#pragma unroll
        for (int np = 0; np < 2; np++) {
            float d0[8][4], d1[8][4];
#pragma unroll
            for (int nt = 0; nt < 8; nt++)
#pragma unroll
                for (int c = 0; c < 4; c++) { d0[nt][c] = 0.f; d1[nt][c] = 0.f; }
#pragma unroll
            for (int kt = 0; kt < 8; kt++) {
                uint4 Bv[4];
#pragma unroll
                for (int q = 0; q < 4; q++)
                    Bv[q] = Bf[(kt * 8 + np * 4 + q) * 32 + l];
#pragma unroll
                for (int q = 0; q < 4; q++) {
                    mma16816h(d0[q * 2 + 0], Af0[kt][0], Af0[kt][1], Af0[kt][2], Af0[kt][3], Bv[q].x, Bv[q].y);
                    mma16816h(d0[q * 2 + 1], Af0[kt][0], Af0[kt][1], Af0[kt][2], Af0[kt][3], Bv[q].z, Bv[q].w);
                    mma16816h(d1[q * 2 + 0], Af1[kt][0], Af1[kt][1], Af1[kt][2], Af1[kt][3], Bv[q].x, Bv[q].y);
                    mma16816h(d1[q * 2 + 1], Af1[kt][0], Af1[kt][1], Af1[kt][2], Af1[kt][3], Bv[q].z, Bv[q].w);
                }
            }
            // epilogue: silu via f16x2 tanh (h fp32, multiply fp32)
#pragma unroll
            for (int nt = 0; nt < 8; nt++) {
                int ntg = np * 8 + nt;
                float2 b2v = b2R2[ntg * 4 + t3];  // pre-halved
                float4 w3v = W3R4[ntg * 4 + t3];
                // block 0 (subs 0,1)
                {
                    float hx0 = fmaf(d0[nt][0], 0.5f, b2v.x);
                    float hx1 = fmaf(d0[nt][1], 0.5f, b2v.y);
                    float hx2 = fmaf(d0[nt][2], 0.5f, b2v.x);
                    float hx3 = fmaf(d0[nt][3], 0.5f, b2v.y);
                    uint32_t thA = tanh2u(cvt2h(hx1, hx0));
                    uint32_t thB = tanh2u(cvt2h(hx3, hx2));
                    float2 tA = __half22float2(u2h2(thA));
                    float2 tB = __half22float2(u2h2(thB));
                    float x0 = fmaf(hx0, tA.x, hx0);
                    float x1 = fmaf(hx1, tA.y, hx1);
                    float x2 = fmaf(hx2, tB.x, hx2);
                    float x3 = fmaf(hx3, tB.y, hx3);
                    acc0[0] += x0 * w3v.x + x1 * w3v.z;
                    acc1[0] += x0 * w3v.y + x1 * w3v.w;
                    acc0[1] += x2 * w3v.x + x3 * w3v.z;
                    acc1[1] += x2 * w3v.y + x3 * w3v.w;
                }
                // block 1 (subs 2,3)
                {
                    float hx0 = fmaf(d1[nt][0], 0.5f, b2v.x);
                    float hx1 = fmaf(d1[nt][1], 0.5f, b2v.y);
                    float hx2 = fmaf(d1[nt][2], 0.5f, b2v.x);
                    float hx3 = fmaf(d1[nt][3], 0.5f, b2v.y);
                    uint32_t thA = tanh2u(cvt2h(hx1, hx0));
                    uint32_t thB = tanh2u(cvt2h(hx3, hx2));
                    float2 tA = __half22float2(u2h2(thA));
                    float2 tB = __half22float2(u2h2(thB));
                    float x0 = fmaf(hx0, tA.x, hx0);
                    float x1 = fmaf(hx1, tA.y, hx1);
                    float x2 = fmaf(hx2, tB.x, hx2);
                    float x3 = fmaf(hx3, tB.y, hx3);
                    acc0[2] += x0 * w3v.x + x1 * w3v.z;
                    acc1[2] += x0 * w3v.y + x1 * w3v.w;
                    acc0[3] += x2 * w3v.x + x3 * w3v.z;
                    acc1[3] += x2 * w3v.y + x3 * w3v.w;
                }
            }
        }

        // ---- quad reduction (all lanes get sums) ----
#pragma unroll
        for (int sub = 0; sub < 4; sub++) {
            acc0[sub] += __shfl_xor_sync(0xffffffffu, acc0[sub], 1);
            acc1[sub] += __shfl_xor_sync(0xffffffffu, acc1[sub], 1);
            acc0[sub] += __shfl_xor_sync(0xffffffffu, acc0[sub], 2);
            acc1[sub] += __shfl_xor_sync(0xffffffffu, acc1[sub], 2);
            acc0[sub] += b3_0;
            acc1[sub] += b3_1;
        }

        // ---- pairwise mbarrier exchange (double-buffered) ----
        int buf = i & 1;
        uint32_t par = (i >> 1) & 1;
        int bufo = buf * 256;
        if (t3 == 0) {
#pragma unroll
            for (int sub = 0; sub < 4; sub++)
                psum2[bufo + m * 128 + s0 + sub * 8] = make_float2(acc0[sub], acc1[sub]);
            mbar_arrive(buf ? myBar1 : myBar0);
        }
        mbar_wait(buf ? peerBar1 : peerBar0, par);

#pragma unroll
        for (int sub = 0; sub < 4; sub++) {
            float2 ov = psum2[bufo + (1 - m) * 128 + s0 + sub * 8];
            int gs = blockBase + s0 + sub * 8;
            zS0[sub] += (acc0[sub] + ov.x) * dt + xi[sub].x * cf;
            zS1[sub] += (acc1[sub] + ov.y) * dt + xi[sub].y * cf;
            if (t3 == 0) {
                if (m == 0) outUS[io + gs] = make_float2(acc0[sub], acc1[sub]);
                else        outTraj[(long long)(i + 1) * N_SAMP + gs] = make_float2(zS0[sub], zS1[sub]);
            }
        }
    }
}

// ---------------------------------------------------------------------------
extern "C" void kernel_launch(void* const* d_in, const int* in_sizes, int n_in,
                              void* d_out, int out_size)
{
    const float* z0       = (const float*)d_in[0];
    const float* pctx     = (const float*)d_in[1];
    const float* cctx     = (const float*)d_in[2];
    const float* times    = (const float*)d_in[3];
    const float* noise    = (const float*)d_in[4];
    const float* freqs    = (const float*)d_in[5];
    const float* dW1      = (const float*)d_in[6];
    const float* db1      = (const float*)d_in[7];
    const float* dW2      = (const float*)d_in[8];
    const float* db2      = (const float*)d_in[9];
    const float* dW3      = (const float*)d_in[10];
    const float* db3      = (const float*)d_in[11];
    const float* cW1      = (const float*)d_in[12];
    const float* cb1      = (const float*)d_in[13];
    const float* cW2      = (const float*)d_in[14];
    const float* cb2      = (const float*)d_in[15];
    const float* cW3      = (const float*)d_in[16];
    const float* cb3      = (const float*)d_in[17];
    const float* log_diff = (const float*)d_in[18];
    float* out = (float*)d_out;

    // Bf 2*32KB + baseR 2*64KB + wzR 2KB + b2R 1KB + W3R 2KB + psum 4KB + mbars 128B
    const int smemB = 2 * 32768 + 2 * 65536 + 512 * 4 + 256 * 4 + 512 * 4 + 512 * 8 + 128;
    cudaFuncSetAttribute(sde_kernel, cudaFuncAttributeMaxDynamicSharedMemorySize, smemB);

    prep_kernel<<<1, 128>>>(times, freqs, dW1, db1, cW1, cb1, log_diff, out);
    sde_kernel<<<N_SAMP / SPB, NTHREADS, smemB>>>(z0, pctx, cctx, noise,
                                                  dW1, dW2, db2, dW3, db3,
                                                  cW1, cW2, cb2, cW3, cb3, out);
}

// round 16
// speedup vs baseline: 1.1727x; 1.1727x over previous
#include <cuda_runtime.h>
#include <cuda_bf16.h>
#include <cuda_fp16.h>
#include <cstdint>

#define N_SAMP   262144
#define ZD       2
#define CTX      128
#define HID      128
#define TEMB     32
#define NSTEPS   50
#define SPB      128     // samples per block
#define NTHREADS 512     // 16 warps: 8 diffusion + 8 cnf, 16 samples each

// output layout: traj [51,N,2] | us [50,N,2] | times [51]
#define US_OFF    ((long long)(NSTEPS+1) * N_SAMP * ZD)
#define TAIL_OFF  (US_OFF + (long long)NSTEPS * N_SAMP * ZD)

// per-step tw constants (PRE-HALVED fp32), permuted into per-lane fragment order:
// idx = i*128 + kt*16 + t*4 + comp,  comp = reg*2 + half  (k = kt*16 + 2t + reg*8 + half)
__device__ float g_twd[NSTEPS * HID];
__device__ float g_twc[NSTEPS * HID];
__device__ float g_dts[NSTEPS];
__device__ float g_coef[NSTEPS];

typedef unsigned long long u64;

__device__ __forceinline__ __half2 u2h2(uint32_t u) { return *reinterpret_cast<__half2*>(&u); }

// pack two fp32 -> fp16x2: lower half = 'even', upper = 'odd'
__device__ __forceinline__ uint32_t cvt2h(float odd_k, float even_k) {
    uint32_t r; asm("cvt.rn.f16x2.f32 %0, %1, %2;" : "=r"(r) : "f"(odd_k), "f"(even_k)); return r;
}
__device__ __forceinline__ uint32_t tanh2u(uint32_t x) {
    uint32_t r; asm("tanh.approx.f16x2 %0, %1;" : "=r"(r) : "r"(x)); return r;
}
// packed fp32x2 helpers (exact IEEE fp32 per lane)
__device__ __forceinline__ u64 f2pack(float a, float b) {
    u64 r; asm("mov.b64 %0, {%1, %2};" : "=l"(r) : "f"(a), "f"(b)); return r;
}
__device__ __forceinline__ void f2unpack(u64 v, float& a, float& b) {
    asm("mov.b64 {%0, %1}, %2;" : "=f"(a), "=f"(b) : "l"(v));
}
__device__ __forceinline__ u64 ffma2(u64 a, u64 b, u64 c) {
    u64 d; asm("fma.rn.f32x2 %0, %1, %2, %3;" : "=l"(d) : "l"(a), "l"(b), "l"(c)); return d;
}
__device__ __forceinline__ u64 fadd2(u64 a, u64 b) {
    u64 d; asm("add.rn.f32x2 %0, %1, %2;" : "=l"(d) : "l"(a), "l"(b)); return d;
}
__device__ __forceinline__ void mma16816h(float* d, uint32_t a0, uint32_t a1,
                                          uint32_t a2, uint32_t a3,
                                          uint32_t b0, uint32_t b1) {
    asm volatile("mma.sync.aligned.m16n8k16.row.col.f32.f16.f16.f32 "
                 "{%0,%1,%2,%3}, {%4,%5,%6,%7}, {%8,%9}, {%0,%1,%2,%3};"
                 : "+f"(d[0]), "+f"(d[1]), "+f"(d[2]), "+f"(d[3])
                 : "r"(a0), "r"(a1), "r"(a2), "r"(a3), "r"(b0), "r"(b1));
}
__device__ __forceinline__ void mbar_init(uint32_t addr, uint32_t cnt) {
    asm volatile("mbarrier.init.shared.b64 [%0], %1;" :: "r"(addr), "r"(cnt) : "memory");
}
__device__ __forceinline__ void mbar_arrive(uint32_t addr) {
    asm volatile("mbarrier.arrive.release.cta.shared::cta.b64 _, [%0];" :: "r"(addr) : "memory");
}
__device__ __forceinline__ void mbar_wait(uint32_t addr, uint32_t parity) {
    asm volatile("{\n\t"
                 ".reg .pred P1;\n\t"
                 "WAIT_%=:\n\t"
                 "mbarrier.try_wait.parity.acquire.cta.shared::cta.b64 P1, [%0], %1, 0x989680;\n\t"
                 "@P1 bra.uni DONE_%=;\n\t"
                 "bra.uni WAIT_%=;\n\t"
                 "DONE_%=:\n\t"
                 "}"
                 :: "r"(addr), "r"(parity) : "memory");
}

// fragment position helpers (k within 128): kt = k>>4, kr = k&15
// t = (kr&7)>>1, reg = (kr>>3)&1, half = kr&1, comp = reg*2 + half
__host__ __device__ __forceinline__ int frag_comp(int kr) { return (((kr >> 3) & 1) << 1) | (kr & 1); }

// ---------------------------------------------------------------------------
// Kernel A: per-step constants (PRE-HALVED tw, permuted) + times tail
// ---------------------------------------------------------------------------
__global__ void prep_kernel(const float* __restrict__ times,
                            const float* __restrict__ freqs,
                            const float* __restrict__ dW1, const float* __restrict__ db1,
                            const float* __restrict__ cW1, const float* __restrict__ cb1,
                            const float* __restrict__ log_diff,
                            float* __restrict__ out)
{
    __shared__ float temb[TEMB];
    int tid = threadIdx.x;  // 128 threads, tid = k
    if (tid < NSTEPS + 1) out[TAIL_OFF + tid] = times[tid];
    int kt = tid >> 4, kr = tid & 15;
    int pidx = kt * 16 + ((kr & 7) >> 1) * 4 + frag_comp(kr);  // permuted position
    float gb = log1pf(__expf(log_diff[0]));  // softplus
    for (int i = 0; i < NSTEPS; i++) {
        float t = times[i];
        __syncthreads();
        if (tid < TEMB / 2) {
            float a = 6.2831853071795864f * t * freqs[tid];
            temb[tid]            = sinf(a);
            temb[tid + TEMB / 2] = cosf(a);
        }
        __syncthreads();
        float ad = db1[tid], ac = cb1[tid];
#pragma unroll 8
        for (int mm = 0; mm < TEMB; mm++) {
            float tv = temb[mm];
            ad += tv * dW1[(ZD + CTX + mm) * HID + tid];
            ac += tv * cW1[(ZD + CTX + mm) * HID + tid];
        }
        g_twd[i * HID + pidx] = 0.5f * ad;   // pre-halved (fp32, exact rescale)
        g_twc[i * HID + pidx] = 0.5f * ac;
        if (tid == 0) {
            float dt = times[i + 1] - t;
            g_dts[i]  = dt;
            g_coef[i] = gb * (1.0f - t) * sqrtf(fmaxf(dt, 1e-12f));
        }
    }
}

// ---------------------------------------------------------------------------
// base = ctx @ W1[2:130] for one group of 8 samples, ctx read from GMEM (fp32)
// ---------------------------------------------------------------------------
__device__ __forceinline__ void compute_base(float* __restrict__ dst,
                                             const float* __restrict__ ctxg,
                                             const float* __restrict__ W1,
                                             int grp, int l)
{
    float acc[8][4];
#pragma unroll
    for (int s8 = 0; s8 < 8; s8++)
#pragma unroll
        for (int c = 0; c < 4; c++) acc[s8][c] = 0.f;
#pragma unroll 2
    for (int r = 0; r < CTX; r++) {
        float w1v[4];
#pragma unroll
        for (int c = 0; c < 4; c++) w1v[c] = W1[(ZD + r) * HID + l + 32 * c];
#pragma unroll
        for (int s8 = 0; s8 < 8; s8++) {
            float a = __ldg(&ctxg[(long long)(grp * 8 + s8) * HID + r]);
#pragma unroll
            for (int c = 0; c < 4; c++) acc[s8][c] += a * w1v[c];
        }
    }
#pragma unroll
    for (int s8 = 0; s8 < 8; s8++)
#pragma unroll
        for (int c = 0; c < 4; c++)
            dst[(grp * 8 + s8) * HID + l + 32 * c] = acc[s8][c];
}

// ---------------------------------------------------------------------------
// Kernel B: persistent 50-step SDE, fp16 tensor-core layer-2, SPB=128.
// R14 structure (16 warps, 16 samples/warp, pairwise mbarrier handshake) with:
//  - base stored split into A-row/B-row halves -> conflict-free 4-wf LDS.128
//  - layer-1 h computed in packed fp32x2 (bit-identical fp32 rounding)
// SMEM: BfD(32K) BfC(32K) baseRD(64K) baseRC(64K) + tables + psum ~ 206KB.
// ---------------------------------------------------------------------------
__global__ void __launch_bounds__(NTHREADS, 1)
sde_kernel(const float* __restrict__ z0,
           const float* __restrict__ pctx, const float* __restrict__ cctx,
           const float* __restrict__ noise,
           const float* __restrict__ dW1, const float* __restrict__ dW2,
           const float* __restrict__ db2, const float* __restrict__ dW3,
           const float* __restrict__ db3,
           const float* __restrict__ cW1, const float* __restrict__ cW2,
           const float* __restrict__ cb2, const float* __restrict__ cW3,
           const float* __restrict__ cb3,
           float* __restrict__ out)
{
    extern __shared__ float sm[];
    uint4* BfD    = (uint4*)sm;              // 8kt*8ntp*32lane uint4 = 32KB
    uint4* BfC    = BfD + 2048;              // 32KB
    float* baseRD = (float*)(BfC + 2048);    // [hi8][ (swg*8+kt)*32+lane ][comp] = 64KB
    float* baseRC = baseRD + 16384;          // 64KB
    float* wzRs   = baseRC + 16384;          // [mlp][row][kt][t] float4 = 512 f (pre-halved)
    float* b2Rs   = wzRs + 512;              // [mlp][ntg][t] float2 = 256 f (pre-halved)
    float* W3Rs   = b2Rs + 256;              // [mlp][ntg][t] float4 = 512 f
    float2* psum2 = (float2*)(W3Rs + 512);   // [2 buf][2 mlp][128] float2 = 8KB
    // mbarriers: [2 mlp][8 wg][2 buf] u64 = 256B
    unsigned long long* mbars = (unsigned long long*)(psum2 + 512);

    int tid = threadIdx.x;
    int w = tid >> 5, l = tid & 31;
    int m  = w & 1;        // 0 = diffusion (u), 1 = cnf (f)  [SMSP-aware map]
    int wg = w >> 1;       // sample group of 16 (0..7)
    int t3 = l & 3;        // quad thread
    int g  = l >> 2;       // row 0-7 (sample A); sample B = row g+8
    int blockBase = blockIdx.x * SPB;
    int sA = wg * 16 + g;
    int sB = sA + 8;
    int gsA = blockBase + sA;
    int gsB = blockBase + sB;

    // ================= phase 1 =================
    // 1) base in old [s][k] layout, ctx read directly from gmem
    {
        const float* ctxg = (m ? cctx : pctx) + (long long)blockBase * HID;
        float* dst = m ? baseRC : baseRD;
        compute_base(dst, ctxg, m ? cW1 : dW1, wg * 2,     l);
        compute_base(dst, ctxg, m ? cW1 : dW1, wg * 2 + 1, l);
    }
    __syncthreads();
    // 2) in-place permute base -> SPLIT fragment order, PRE-HALVED (fp32):
    //    ni = hi8*8192 + ((swg*8 + kt)*32 + lane)*4 + comp
    {
        float tmpv[32];
#pragma unroll
        for (int a = 0; a < 2; a++) {
            float* arr = a ? baseRC : baseRD;
#pragma unroll
            for (int q = 0; q < 32; q++) tmpv[q] = arr[tid * 32 + q];
            __syncthreads();
#pragma unroll
            for (int q = 0; q < 32; q++) {
                int idx = tid * 32 + q;
                int s = idx >> 7, k = idx & 127;
                int swg = s >> 4, srow = s & 15;
                int hi8 = srow >> 3, gg = srow & 7;
                int kt = k >> 4, kr = k & 15;
                int lane = gg * 4 + ((kr & 7) >> 1);
                int ni = hi8 * 8192 + ((swg * 8 + kt) * 32 + lane) * 4 + frag_comp(kr);
                arr[ni] = 0.5f * tmpv[q];
            }
            __syncthreads();
        }
    }
    // 3) W2 -> SINGLE fp16 in B-fragment layout (two ntg per uint4); tables; mbars
    {
        unsigned short* bD16 = (unsigned short*)BfD;
        unsigned short* bC16 = (unsigned short*)BfC;
        for (int e = tid; e < HID * HID; e += NTHREADS) {
            int k = e >> 7, j = e & 127;
            int kt = k >> 4, kr = k & 15;
            int reg = (kr >> 3) & 1, half = kr & 1;
            int lane = (j & 7) * 4 + ((kr & 7) >> 1);
            int ntg = j >> 3;
            int ntp = ntg >> 1, sub = ntg & 1;
            int slot = ((kt * 8 + ntp) * 32 + lane) * 4 + sub * 2 + reg;
            bD16[slot * 2 + half] = __half_as_ushort(__float2half_rn(dW2[e]));
            bC16[slot * 2 + half] = __half_as_ushort(__float2half_rn(cW2[e]));
        }
        // wzR (PRE-HALVED): [mlp][row][kt][t][comp]
        for (int idx = tid; idx < 2 * 2 * HID; idx += NTHREADS) {
            int mlp = idx >> 8, row = (idx >> 7) & 1, k = idx & 127;
            int kt = k >> 4, kr = k & 15;
            float v = 0.5f * (mlp ? cW1 : dW1)[row * HID + k];
            wzRs[((mlp * 2 + row) * 8 + kt) * 16 + ((kr & 7) >> 1) * 4 + frag_comp(kr)] = v;
        }
        // b2R (PRE-HALVED): [mlp][ntg][t][half]   (j = ntg*8 + 2t + half)
        for (int idx = tid; idx < 2 * HID; idx += NTHREADS) {
            int mlp = idx >> 7, j = idx & 127;
            float v = 0.5f * (mlp ? cb2 : db2)[j];
            b2Rs[(mlp * 16 + (j >> 3)) * 8 + ((j & 7) >> 1) * 2 + (j & 1)] = v;
        }
        // W3R: [mlp][ntg][t][(j&1)*2 + d]
        for (int idx = tid; idx < 2 * HID * ZD; idx += NTHREADS) {
            int mlp = idx >> 8, j = (idx >> 1) & 127, d = idx & 1;
            float v = (mlp ? cW3 : dW3)[j * ZD + d];
            W3Rs[(mlp * 16 + (j >> 3)) * 16 + ((j & 7) >> 1) * 4 + (j & 1) * 2 + d] = v;
        }
        // 32 mbarriers, arrive count = 8 (the t3==0 lanes of one warp)
        if (tid < 32)
            mbar_init((uint32_t)__cvta_generic_to_shared(&mbars[tid]), 8);
    }
    __syncthreads();

    // ================= per-warp constant pointers / regs =================
    const uint4*      Bf   = m ? BfC : BfD;
    const ulonglong2* bA2  = (const ulonglong2*)(m ? baseRC : baseRD);         // A-rows
    const ulonglong2* bB2  = (const ulonglong2*)((m ? baseRC : baseRD) + 8192); // B-rows
    const ulonglong2* tw2  = (const ulonglong2*)(m ? g_twc : g_twd);
    const ulonglong2* wz02 = (const ulonglong2*)wzRs + (m * 2 + 0) * 32;
    const ulonglong2* wz12 = (const ulonglong2*)wzRs + (m * 2 + 1) * 32;
    const float2* b2R2  = (const float2*)b2Rs + m * 64;
    const float4* W3R4  = (const float4*)W3Rs + m * 64;
    const float2* noise2 = (const float2*)noise;
    float2* outTraj = (float2*)out;
    float2* outUS   = (float2*)(out + US_OFF);

    uint32_t myBar0   = (uint32_t)__cvta_generic_to_shared(&mbars[(m * 8 + wg) * 2 + 0]);
    uint32_t myBar1   = (uint32_t)__cvta_generic_to_shared(&mbars[(m * 8 + wg) * 2 + 1]);
    uint32_t peerBar0 = (uint32_t)__cvta_generic_to_shared(&mbars[((1 - m) * 8 + wg) * 2 + 0]);
    uint32_t peerBar1 = (uint32_t)__cvta_generic_to_shared(&mbars[((1 - m) * 8 + wg) * 2 + 1]);

    float b3_0, b3_1;
    { const float* b3 = m ? cb3 : db3; b3_0 = b3[0]; b3_1 = b3[1]; }

    // init z (all 4 lanes of quad hold both samples' z)
    float2 ziA = __ldg(&((const float2*)z0)[gsA]);
    float2 ziB = __ldg(&((const float2*)z0)[gsB]);
    float zA0 = ziA.x, zA1 = ziA.y, zB0 = ziB.x, zB1 = ziB.y;
    if (m == 1 && t3 == 0) { outTraj[gsA] = ziA; outTraj[gsB] = ziB; }

    // ================= 50-step loop (no CTA barrier inside) =================
    for (int i = 0; i < NSTEPS; i++) {
        float dt = g_dts[i], cf = g_coef[i];
        long long io = (long long)i * N_SAMP;
        float2 xiA = __ldg(&noise2[io + gsA]);
        float2 xiB = __ldg(&noise2[io + gsB]);

        // packed z duplicates for fp32x2 layer-1
        u64 zA0d = f2pack(zA0, zA0), zA1d = f2pack(zA1, zA1);
        u64 zB0d = f2pack(zB0, zB0), zB1d = f2pack(zB1, zB1);

        // ---- layer 1 (packed fp32x2 h = x/2; tanh via f16x2; A frags fp16) ----
        uint32_t Af[8][4];
#pragma unroll
        for (int kt = 0; kt < 8; kt++) {
            ulonglong2 bsA = bA2[(wg * 8 + kt) * 32 + l];   // pre-halved
            ulonglong2 bsB = bB2[(wg * 8 + kt) * 32 + l];
            ulonglong2 tw  = __ldg(&tw2[i * 32 + kt * 4 + t3]);  // pre-halved
            ulonglong2 w0  = wz02[kt * 4 + t3];                  // pre-halved
            ulonglong2 w1  = wz12[kt * 4 + t3];
            u64 hA01 = ffma2(zA1d, w1.x, ffma2(zA0d, w0.x, fadd2(bsA.x, tw.x)));
            u64 hA23 = ffma2(zA1d, w1.y, ffma2(zA0d, w0.y, fadd2(bsA.y, tw.y)));
            u64 hB01 = ffma2(zB1d, w1.x, ffma2(zB0d, w0.x, fadd2(bsB.x, tw.x)));
            u64 hB23 = ffma2(zB1d, w1.y, ffma2(zB0d, w0.y, fadd2(bsB.y, tw.y)));
            float hAx, hAy, hAz, hAw, hBx, hBy, hBz, hBw;
            f2unpack(hA01, hAx, hAy); f2unpack(hA23, hAz, hAw);
            f2unpack(hB01, hBx, hBy); f2unpack(hB23, hBz, hBw);
            uint32_t tAu01 = tanh2u(cvt2h(hAy, hAx));
            uint32_t tAu23 = tanh2u(cvt2h(hAw, hAz));
            uint32_t tBu01 = tanh2u(cvt2h(hBy, hBx));
            uint32_t tBu23 = tanh2u(cvt2h(hBw, hBz));
            float2 tA01 = __half22float2(u2h2(tAu01));
            float2 tA23 = __half22float2(u2h2(tAu23));
            float2 tB01 = __half22float2(u2h2(tBu01));
            float2 tB23 = __half22float2(u2h2(tBu23));
            float xAx = fmaf(hAx, tA01.x, hAx);
            float xAy = fmaf(hAy, tA01.y, hAy);
            float xAz = fmaf(hAz, tA23.x, hAz);
            float xAw = fmaf(hAw, tA23.y, hAw);
            float xBx = fmaf(hBx, tB01.x, hBx);
            float xBy = fmaf(hBy, tB01.y, hBy);
            float xBz = fmaf(hBz, tB23.x, hBz);
            float xBw = fmaf(hBw, tB23.y, hBw);
            Af[kt][0] = cvt2h(xAy, xAx);
            Af[kt][1] = cvt2h(xBy, xBx);
            Af[kt][2] = cvt2h(xAw, xAz);
            Af[kt][3] = cvt2h(xBw, xBz);
        }

        // ---- layer 2 + epilogue in two N passes (8 n-tiles each) ----
        float aA0 = 0.f, aA1 = 0.f, aB0 = 0.f, aB1 = 0.f;
#pragma unroll
        for (int np = 0; np < 2; np++) {
            float d[8][4];
#pragma unroll
            for (int nt = 0; nt < 8; nt++)
#pragma unroll
                for (int c = 0; c < 4; c++) d[nt][c] = 0.f;
#pragma unroll
            for (int kt = 0; kt < 8; kt++) {
                uint4 Bv[4];
#pragma unroll
                for (int q = 0; q < 4; q++)
                    Bv[q] = Bf[(kt * 8 + np * 4 + q) * 32 + l];
#pragma unroll
                for (int q = 0; q < 4; q++) {
                    mma16816h(d[q * 2 + 0], Af[kt][0], Af[kt][1], Af[kt][2], Af[kt][3], Bv[q].x, Bv[q].y);
                    mma16816h(d[q * 2 + 1], Af[kt][0], Af[kt][1], Af[kt][2], Af[kt][3], Bv[q].z, Bv[q].w);
                }
            }
            // epilogue: silu via f16x2 tanh (h fp32, multiply fp32)
#pragma unroll
            for (int nt = 0; nt < 8; nt++) {
                int ntg = np * 8 + nt;
                float2 b2v = b2R2[ntg * 4 + t3];  // pre-halved
                float4 w3v = W3R4[ntg * 4 + t3];
                float hx0 = fmaf(d[nt][0], 0.5f, b2v.x);
                float hx1 = fmaf(d[nt][1], 0.5f, b2v.y);
                float hx2 = fmaf(d[nt][2], 0.5f, b2v.x);
                float hx3 = fmaf(d[nt][3], 0.5f, b2v.y);
                uint32_t thA = tanh2u(cvt2h(hx1, hx0));
                uint32_t thB = tanh2u(cvt2h(hx3, hx2));
                float2 tA = __half22float2(u2h2(thA));
                float2 tB = __half22float2(u2h2(thB));
                float x0 = fmaf(hx0, tA.x, hx0);
                float x1 = fmaf(hx1, tA.y, hx1);
                float x2 = fmaf(hx2, tB.x, hx2);
                float x3 = fmaf(hx3, tB.y, hx3);
                aA0 += x0 * w3v.x + x1 * w3v.z;
                aA1 += x0 * w3v.y + x1 * w3v.w;
                aB0 += x2 * w3v.x + x3 * w3v.z;
                aB1 += x2 * w3v.y + x3 * w3v.w;
            }
        }

        // ---- quad reduction (all lanes get sums) ----
        aA0 += __shfl_xor_sync(0xffffffffu, aA0, 1);
        aA1 += __shfl_xor_sync(0xffffffffu, aA1, 1);
        aB0 += __shfl_xor_sync(0xffffffffu, aB0, 1);
        aB1 += __shfl_xor_sync(0xffffffffu, aB1, 1);
        aA0 += __shfl_xor_sync(0xffffffffu, aA0, 2);
        aA1 += __shfl_xor_sync(0xffffffffu, aA1, 2);
        aB0 += __shfl_xor_sync(0xffffffffu, aB0, 2);
        aB1 += __shfl_xor_sync(0xffffffffu, aB1, 2);
        float vA0 = aA0 + b3_0, vA1 = aA1 + b3_1;
        float vB0 = aB0 + b3_0, vB1 = aB1 + b3_1;

        // ---- pairwise mbarrier exchange (double-buffered) ----
        int buf = i & 1;
        uint32_t par = (i >> 1) & 1;
        int bufo = buf * 256;
        if (t3 == 0) {
            psum2[bufo + m * 128 + sA] = make_float2(vA0, vA1);
            psum2[bufo + m * 128 + sB] = make_float2(vB0, vB1);
            mbar_arrive(buf ? myBar1 : myBar0);
        }
        mbar_wait(buf ? peerBar1 : peerBar0, par);
        float2 ovA = psum2[bufo + (1 - m) * 128 + sA];
        float2 ovB = psum2[bufo + (1 - m) * 128 + sB];

        zA0 += (vA0 + ovA.x) * dt + xiA.x * cf;
        zA1 += (vA1 + ovA.y) * dt + xiA.y * cf;
        zB0 += (vB0 + ovB.x) * dt + xiB.x * cf;
        zB1 += (vB1 + ovB.y) * dt + xiB.y * cf;
        if (t3 == 0) {
            if (m == 0) {
                outUS[io + gsA] = make_float2(vA0, vA1);
                outUS[io + gsB] = make_float2(vB0, vB1);
            } else {
                outTraj[(long long)(i + 1) * N_SAMP + gsA] = make_float2(zA0, zA1);
                outTraj[(long long)(i + 1) * N_SAMP + gsB] = make_float2(zB0, zB1);
            }
        }
    }
}

// ---------------------------------------------------------------------------
extern "C" void kernel_launch(void* const* d_in, const int* in_sizes, int n_in,
                              void* d_out, int out_size)
{
    const float* z0       = (const float*)d_in[0];
    const float* pctx     = (const float*)d_in[1];
    const float* cctx     = (const float*)d_in[2];
    const float* times    = (const float*)d_in[3];
    const float* noise    = (const float*)d_in[4];
    const float* freqs    = (const float*)d_in[5];
    const float* dW1      = (const float*)d_in[6];
    const float* db1      = (const float*)d_in[7];
    const float* dW2      = (const float*)d_in[8];
    const float* db2      = (const float*)d_in[9];
    const float* dW3      = (const float*)d_in[10];
    const float* db3      = (const float*)d_in[11];
    const float* cW1      = (const float*)d_in[12];
    const float* cb1      = (const float*)d_in[13];
    const float* cW2      = (const float*)d_in[14];
    const float* cb2      = (const float*)d_in[15];
    const float* cW3      = (const float*)d_in[16];
    const float* cb3      = (const float*)d_in[17];
    const float* log_diff = (const float*)d_in[18];
    float* out = (float*)d_out;

    // Bf 2*32KB + baseR 2*64KB + wzR 2KB + b2R 1KB + W3R 2KB + psum 8KB + mbars 256B
    const int smemB = 2 * 32768 + 2 * 65536 + 512 * 4 + 256 * 4 + 512 * 4 + 512 * 8 + 256;
    cudaFuncSetAttribute(sde_kernel, cudaFuncAttributeMaxDynamicSharedMemorySize, smemB);

    prep_kernel<<<1, 128>>>(times, freqs, dW1, db1, cW1, cb1, log_diff, out);
    sde_kernel<<<N_SAMP / SPB, NTHREADS, smemB>>>(z0, pctx, cctx, noise,
                                                  dW1, dW2, db2, dW3, db3,
                                                  cW1, cW2, cb2, cW3, cb3, out);
}